// round 1
// baseline (speedup 1.0000x reference)
#include <cuda_runtime.h>

#define BN   2048
#define DD   32
#define NIDS 8192
#define KNN  30
#define TI   8
#define NTHR 256

// Scratch (no allocations allowed)
__device__ float g_sq[BN];
__device__ float g_zT[DD * BN];
__device__ float g_loss[BN];
__device__ float g_validf[BN];

__device__ __forceinline__ unsigned long long pack2(float x, float y) {
    unsigned long long r;
    asm("mov.b64 %0, {%1, %2};" : "=l"(r) : "f"(x), "f"(y));
    return r;
}
__device__ __forceinline__ void unpack2(unsigned long long v, float &x, float &y) {
    asm("mov.b64 {%0, %1}, %2;" : "=f"(x), "=f"(y) : "l"(v));
}
__device__ __forceinline__ unsigned long long fma2(unsigned long long a,
                                                   unsigned long long b,
                                                   unsigned long long c) {
    unsigned long long d;
    asm("fma.rn.f32x2 %0, %1, %2, %3;" : "=l"(d) : "l"(a), "l"(b), "l"(c));
    return d;
}

// Kernel 1: squared norms + transpose z -> zT[k][j] for coalesced j-streaming
__global__ void prep_kernel(const float* __restrict__ z) {
    int j = blockIdx.x * blockDim.x + threadIdx.x;
    if (j >= BN) return;
    const float4* zr = (const float4*)(z + j * DD);
    float s = 0.f;
#pragma unroll
    for (int c = 0; c < 8; c++) {
        float4 v = zr[c];
        s += v.x * v.x + v.y * v.y + v.z * v.z + v.w * v.w;
        g_zT[(c * 4 + 0) * BN + j] = v.x;
        g_zT[(c * 4 + 1) * BN + j] = v.y;
        g_zT[(c * 4 + 2) * BN + j] = v.z;
        g_zT[(c * 4 + 3) * BN + j] = v.w;
    }
    g_sq[j] = s;
}

// Kernel 2: each CTA handles TI=8 rows (i) against all 2048 columns (j).
__global__ void __launch_bounds__(NTHR)
main_kernel(const float* __restrict__ z,
            const int* __restrict__ knn,
            const int* __restrict__ sid) {
    // z_i tile: [k][4 packed row-pairs] -> 32 * 2 * 16B = 1KB
    __shared__ ulonglong2 s_zi[DD][2];
    // membership bitsets: 8 rows x 8192 bits = 8KB
    __shared__ unsigned s_bits[TI * 256];
    __shared__ float s_sqi[TI];
    __shared__ float s_rd[NTHR / 32][TI];
    __shared__ float s_rn[NTHR / 32][TI];
    __shared__ unsigned s_ra[NTHR / 32];

    const int t = threadIdx.x;
    const int row0 = blockIdx.x * TI;

    // load z_i tile (256 floats), layout: float index k*8 + r
    {
        int r = t >> 5;
        int k = t & 31;
        ((float*)s_zi)[k * 8 + r] = z[(row0 + r) * DD + k];
    }
    if (t < TI) s_sqi[t] = 0.f;  // placeholder; real value after sync (g_sq ready: prior kernel)
    for (int w = t; w < TI * 256; w += NTHR) s_bits[w] = 0u;
    __syncthreads();
    if (t < TI) s_sqi[t] = g_sq[row0 + t];
    if (t < TI * KNN) {
        int r = t / KNN;
        int kk = t - r * KNN;
        int srow = sid[row0 + r];
        int id = knn[srow * KNN + kk];
        atomicOr(&s_bits[r * 256 + (id >> 5)], 1u << (id & 31));
    }
    __syncthreads();

    float den[TI], num[TI];
#pragma unroll
    for (int r = 0; r < TI; r++) { den[r] = 0.f; num[r] = 0.f; }
    unsigned anyM = 0u;

    for (int j = t; j < BN; j += NTHR) {
        int sj = sid[j];
        unsigned wi = ((unsigned)sj) >> 5;
        unsigned bi = 1u << (sj & 31);
        unsigned m = 0u;
#pragma unroll
        for (int r = 0; r < TI; r++)
            m |= ((s_bits[r * 256 + wi] & bi) ? 1u : 0u) << r;

        float sqj = g_sq[j];

        unsigned long long a0 = 0ull, a1 = 0ull, a2 = 0ull, a3 = 0ull;
#pragma unroll
        for (int k = 0; k < DD; k++) {
            float vj = g_zT[k * BN + j];
            unsigned long long v2 = pack2(vj, vj);
            ulonglong2 p0 = s_zi[k][0];
            ulonglong2 p1 = s_zi[k][1];
            a0 = fma2(p0.x, v2, a0);
            a1 = fma2(p0.y, v2, a1);
            a2 = fma2(p1.x, v2, a2);
            a3 = fma2(p1.y, v2, a3);
        }
        float dot[TI];
        unpack2(a0, dot[0], dot[1]);
        unpack2(a1, dot[2], dot[3]);
        unpack2(a2, dot[4], dot[5]);
        unpack2(a3, dot[6], dot[7]);

#pragma unroll
        for (int r = 0; r < TI; r++) {
            float d2 = fmaf(-2.f, dot[r], s_sqi[r] + sqj);
            d2 = fmaxf(d2, 0.f);
            float dist = d2 * __frsqrt_rn(d2);
            dist = (d2 > 0.f) ? dist : 0.f;
            float e = __expf(-dist);
            bool diag = (j == row0 + r);
            e = diag ? 0.f : e;
            den[r] += e;
            bool msk = (((m >> r) & 1u) != 0u) && !diag;
            num[r] += msk ? e : 0.f;
            anyM |= (msk ? 1u : 0u) << r;
        }
    }

    // intra-warp reduce
#pragma unroll
    for (int r = 0; r < TI; r++) {
#pragma unroll
        for (int off = 16; off > 0; off >>= 1) {
            den[r] += __shfl_xor_sync(0xffffffffu, den[r], off);
            num[r] += __shfl_xor_sync(0xffffffffu, num[r], off);
        }
    }
    anyM = __reduce_or_sync(0xffffffffu, anyM);

    int warp = t >> 5, lane = t & 31;
    if (lane == 0) {
#pragma unroll
        for (int r = 0; r < TI; r++) {
            s_rd[warp][r] = den[r];
            s_rn[warp][r] = num[r];
        }
        s_ra[warp] = anyM;
    }
    __syncthreads();

    if (t < TI) {
        float dsum = 0.f, nsum = 0.f;
        unsigned a = 0u;
#pragma unroll
        for (int w = 0; w < NTHR / 32; w++) {
            dsum += s_rd[w][t];
            nsum += s_rn[w][t];
            a |= s_ra[w];
        }
        bool valid = ((a >> t) & 1u) != 0u;
        float s = nsum / dsum;
        float loss = -__logf(s + 1e-8f);
        g_loss[row0 + t] = valid ? loss : 0.f;
        g_validf[row0 + t] = valid ? 1.f : 0.f;
    }
}

// Kernel 3: final deterministic reduction to the scalar output
__global__ void finish_kernel(float* __restrict__ out) {
    __shared__ float sl[8], sv[8];
    int t = threadIdx.x;
    float tot = 0.f, cnt = 0.f;
    for (int i = t; i < BN; i += 256) {
        tot += g_loss[i];
        cnt += g_validf[i];
    }
#pragma unroll
    for (int off = 16; off > 0; off >>= 1) {
        tot += __shfl_xor_sync(0xffffffffu, tot, off);
        cnt += __shfl_xor_sync(0xffffffffu, cnt, off);
    }
    if ((t & 31) == 0) { sl[t >> 5] = tot; sv[t >> 5] = cnt; }
    __syncthreads();
    if (t == 0) {
        float T = 0.f, C = 0.f;
#pragma unroll
        for (int w = 0; w < 8; w++) { T += sl[w]; C += sv[w]; }
        out[0] = (C > 0.f) ? (T / C) : 0.f;
    }
}

extern "C" void kernel_launch(void* const* d_in, const int* in_sizes, int n_in,
                              void* d_out, int out_size) {
    const float* z   = (const float*)d_in[0];
    const int*   knn = (const int*)d_in[1];
    const int*   sid = (const int*)d_in[2];
    (void)in_sizes; (void)n_in; (void)out_size;

    prep_kernel<<<BN / NTHR, NTHR>>>(z);
    main_kernel<<<BN / TI, NTHR>>>(z, knn, sid);
    finish_kernel<<<1, 256>>>((float*)d_out);
}